// round 17
// baseline (speedup 1.0000x reference)
#include <cuda_runtime.h>
#include <cuda_bf16.h>
#include <cuda_fp16.h>
#include <cstdint>
#include <cstring>
#include <math.h>

#define TT 128
#define NN 2048
#define HH 128
#define ROWS (TT*NN)          // 262144

// ---------------- scratch (device globals; no runtime allocation) ----------------
__device__ __nv_bfloat16 g_ws[262144];     // weight container (f16 bits for W_eff, Whh)
__device__ float g_m1[384*128];            // Wih @ W2 (fp32)
__device__ float g_t1[384];                // Wih @ b2
__device__ float g_beff[384];              // composed bias

// offsets (16-bit elements) into g_ws
#define WIHH 65536
#define WHHH 163840

namespace {
struct ModuleLoader {
    ModuleLoader() {
        void* p = nullptr;
        cudaGetSymbolAddress(&p, g_ws);
        cudaGetSymbolAddress(&p, g_m1);
        cudaGetSymbolAddress(&p, g_t1);
        cudaGetSymbolAddress(&p, g_beff);
    }
};
ModuleLoader g_module_loader_;
}

// ---------------- PTX helpers ----------------
__device__ __forceinline__ uint32_t smem_u32(const void* p) {
    uint32_t a;
    asm("{ .reg .u64 t; cvta.to.shared.u64 t, %1; cvt.u32.u64 %0, t; }" : "=r"(a) : "l"(p));
    return a;
}
__device__ __forceinline__ void ldm_x4(uint32_t* r, uint32_t addr) {
    asm volatile("ldmatrix.sync.aligned.m8n8.x4.shared.b16 {%0,%1,%2,%3}, [%4];"
                 : "=r"(r[0]), "=r"(r[1]), "=r"(r[2]), "=r"(r[3]) : "r"(addr));
}
__device__ __forceinline__ void mma16816h(float4& c, const uint32_t* a, const uint32_t* b) {
    asm volatile("mma.sync.aligned.m16n8k16.row.col.f32.f16.f16.f32 "
                 "{%0,%1,%2,%3}, {%4,%5,%6,%7}, {%8,%9}, {%0,%1,%2,%3};"
                 : "+f"(c.x), "+f"(c.y), "+f"(c.z), "+f"(c.w)
                 : "r"(a[0]), "r"(a[1]), "r"(a[2]), "r"(a[3]), "r"(b[0]), "r"(b[1]));
}
__device__ __forceinline__ float tanh_ap(float v) {
    float r;
    asm("tanh.approx.f32 %0, %1;" : "=f"(r) : "f"(v));
    return r;
}
__device__ __forceinline__ float sigmoid_ap(float v) {
    return fmaf(tanh_ap(0.5f * v), 0.5f, 0.5f);
}

// SW128 blocked-atom layout (atom = 8 rows x 64 b16 = 1024B); atomsPerCB = rows/8
__device__ __forceinline__ uint32_t sw_off(int row, int colb16, int atomsPerCB) {
    uint32_t atom = (uint32_t)((row >> 3) + (colb16 >> 6) * atomsPerCB);
    uint32_t byte = atom * 1024u + (uint32_t)(row & 7) * 128u + (uint32_t)(colb16 & 63) * 2u;
    return byte ^ ((byte >> 3) & 0x70u);
}

// fp32x4 -> f16x4, store 8B into swizzled smem
__device__ __forceinline__ void sts_h4(char* base, int row, int c0, float4 v, int atoms) {
    __half2 p0 = __floats2half2_rn(v.x, v.y);
    __half2 p1 = __floats2half2_rn(v.z, v.w);
    uint32_t u0, u1; memcpy(&u0, &p0, 4); memcpy(&u1, &p1, 4);
    *reinterpret_cast<uint2*>(base + sw_off(row, c0, atoms)) = make_uint2(u0, u1);
}

// ---------------- weight composition prep (fp32) ----------------
__global__ void __launch_bounds__(128) prep_m1(const float* __restrict__ Wih,
                                               const float* __restrict__ W2,
                                               const float* __restrict__ b2,
                                               float* __restrict__ m1,
                                               float* __restrict__ t1)
{
    int j = blockIdx.x, i = threadIdx.x;
    __shared__ float wrow[128];
    __shared__ float red[128];
    wrow[i] = Wih[j * 128 + i];
    __syncthreads();
    float s = 0.f;
    #pragma unroll 8
    for (int k = 0; k < 128; k++) s += wrow[k] * W2[k * 128 + i];
    m1[j * 128 + i] = s;
    red[i] = wrow[i] * b2[i];
    __syncthreads();
    if (i < 64) red[i] += red[i + 64];
    __syncthreads();
    if (i < 32) {
        float v = red[i] + red[i + 32];
        #pragma unroll
        for (int o = 16; o > 0; o >>= 1) v += __shfl_down_sync(0xffffffffu, v, o);
        if (i == 0) t1[j] = v;
    }
}

// W_eff = M1 @ W1 -> f16; b_eff = bih + t1 + M1 @ b1
__global__ void __launch_bounds__(128) prep_meff(const float* __restrict__ m1,
                                                 const float* __restrict__ W1,
                                                 const float* __restrict__ b1,
                                                 const float* __restrict__ bih,
                                                 const float* __restrict__ t1,
                                                 __nv_bfloat16* __restrict__ ws,
                                                 float* __restrict__ beff)
{
    int j = blockIdx.x, i = threadIdx.x;
    __shared__ float mrow[128];
    __shared__ float red[128];
    mrow[i] = m1[j * 128 + i];
    __syncthreads();
    float s = 0.f;
    #pragma unroll 8
    for (int k = 0; k < 128; k++) s += mrow[k] * W1[k * 128 + i];
    __half hv = __float2half_rn(s);
    unsigned short hb; memcpy(&hb, &hv, 2);
    reinterpret_cast<unsigned short*>(ws)[WIHH + j * 128 + i] = hb;
    red[i] = mrow[i] * b1[i];
    __syncthreads();
    if (i < 64) red[i] += red[i + 64];
    __syncthreads();
    if (i < 32) {
        float v = red[i] + red[i + 32];
        #pragma unroll
        for (int o = 16; o > 0; o >>= 1) v += __shfl_down_sync(0xffffffffu, v, o);
        if (i == 0) beff[j] = bih[j] + t1[j] + v;
    }
}

// Whh -> f16
__global__ void __launch_bounds__(256) prep_whh(const float* __restrict__ Whh,
                                                __nv_bfloat16* __restrict__ ws)
{
    int idx = blockIdx.x * 256 + threadIdx.x;   // 49152
    __half hv = __float2half_rn(Whh[idx]);
    unsigned short b; memcpy(&b, &hv, 2);
    reinterpret_cast<unsigned short*>(ws)[WHHH + idx] = b;
}

// ---------------- grand fused scan: fused r/z accumulators, 1 sync/step ----------------
// 16 batch rows per block (128 blocks), 512 threads (16 warps).
#define SCN_WHH  0
#define SCN_WEF  98304
#define SCN_HH   196608                  // 2 x 4096
#define HH_BUF   4096
#define SCN_XH   204800                  // 2 x 4096
#define XH_BUF   4096
#define SCN_LNT  212992                  // 2 x 8448
#define LNT_BUF  8448
#define SCN_L1W  229888                  // 128 f32
#define SCN_L1B  230400
#define SCN_L2W  230912
#define SCN_L2B  231424
#define SCAN_SMEM 231936

// fused dual-chain LN reduction: returns (mean, rstd)
__device__ __forceinline__ void ln_stats(float4 v, float& m, float& rstd) {
    float s  = v.x + v.y + v.z + v.w;
    float s2 = fmaf(v.x, v.x, fmaf(v.y, v.y, fmaf(v.z, v.z, v.w * v.w)));
    #pragma unroll
    for (int o = 16; o > 0; o >>= 1) {
        s  += __shfl_xor_sync(0xffffffffu, s,  o);
        s2 += __shfl_xor_sync(0xffffffffu, s2, o);
    }
    m = s * 0.0078125f;
    float var = fmaf(-m, m, s2 * 0.0078125f);
    rstd = rsqrtf(var + 1e-5f);
}

// LN apply with params from smem (float4 views)
__device__ __forceinline__ float4 ln_apply(float4 v, float m, float rstd,
                                           const char* smw, const char* smbp, int lane) {
    float4 w4 = *reinterpret_cast<const float4*>(smw + lane * 16);
    float4 b4 = *reinterpret_cast<const float4*>(smbp + lane * 16);
    float4 o4;
    o4.x = (v.x - m) * rstd * w4.x + b4.x;
    o4.y = (v.y - m) * rstd * w4.y + b4.y;
    o4.z = (v.z - m) * rstd * w4.z + b4.z;
    o4.w = (v.w - m) * rstd * w4.w + b4.w;
    return o4;
}

__global__ void __launch_bounds__(512) scan_mega(const float* __restrict__ x,
                                                 const float* __restrict__ hxs,
                                                 const float* __restrict__ masks,
                                                 const __nv_bfloat16* __restrict__ ws,
                                                 const float* __restrict__ beff,
                                                 const float* __restrict__ bhh,
                                                 const float* __restrict__ ln1w,
                                                 const float* __restrict__ ln1b,
                                                 const float* __restrict__ ln2w,
                                                 const float* __restrict__ ln2b,
                                                 float* __restrict__ out,
                                                 float* __restrict__ hT)
{
    extern __shared__ __align__(1024) char dynsm[];
    char* sm = dynsm;
    const uint32_t smb = smem_u32(sm);
    const int tid  = threadIdx.x;
    const int wid  = tid >> 5;
    const int lane = tid & 31;
    const int n0   = blockIdx.x * 16;

    // stage Whh + W_eff f16 (each 384x128, swizzled, atoms=48)
    {
        const uint4* whh = reinterpret_cast<const uint4*>(
            reinterpret_cast<const unsigned short*>(ws) + WHHH);
        const uint4* wef = reinterpret_cast<const uint4*>(
            reinterpret_cast<const unsigned short*>(ws) + WIHH);
        #pragma unroll
        for (int it = 0; it < 12; it++) {
            int i = tid + it * 512;                // 384 rows x 16 uint4
            int row = i >> 4, c8 = i & 15;
            uint32_t off = sw_off(row, c8 * 8, 48);
            *reinterpret_cast<uint4*>(sm + SCN_WHH + off) = whh[i];
            *reinterpret_cast<uint4*>(sm + SCN_WEF + off) = wef[i];
        }
    }
    // LN params to smem
    if (tid < 128) {
        reinterpret_cast<float*>(sm + SCN_L1W)[tid] = ln1w[tid];
        reinterpret_cast<float*>(sm + SCN_L1B)[tid] = ln1b[tid];
        reinterpret_cast<float*>(sm + SCN_L2W)[tid] = ln2w[tid];
        reinterpret_cast<float*>(sm + SCN_L2B)[tid] = ln2b[tid];
    }

    const int qrow = lane >> 2, qcol = (lane & 3) * 2;
    const int jbase = wid * 8;
    const int lr = lane & 7, lg = lane >> 3;
    const int a_row = lr + ((lg & 1) << 3), akg = lg >> 1;
    const int b_ks_half = lg >> 1, b_kg = lg & 1;

    // h state
    float h[2][2];
    #pragma unroll
    for (int ri = 0; ri < 2; ri++) {
        float2 v = *reinterpret_cast<const float2*>(
            &hxs[(size_t)(n0 + qrow + ri * 8) * 128 + jbase + qcol]);
        h[ri][0] = v.x; h[ri][1] = v.y;
    }
    // biases: r,z combined (gi+gh accumulate together); n split
    float brz[2][2], bngi[2], bngh[2];
    #pragma unroll
    for (int g = 0; g < 2; g++) {
        float2 ve = *reinterpret_cast<const float2*>(&beff[g * 128 + jbase + qcol]);
        float2 vh = *reinterpret_cast<const float2*>(&bhh[g * 128 + jbase + qcol]);
        brz[g][0] = ve.x + vh.x; brz[g][1] = ve.y + vh.y;
    }
    {
        float2 ve = *reinterpret_cast<const float2*>(&beff[256 + jbase + qcol]);
        float2 vh = *reinterpret_cast<const float2*>(&bhh[256 + jbase + qcol]);
        bngi[0] = ve.x; bngi[1] = ve.y;
        bngh[0] = vh.x; bngh[1] = vh.y;
    }

    float mn0 = masks[n0 + qrow];
    float mn1 = masks[n0 + qrow + 8];

    // ---- prologue: LN1(x(0)) -> xh buf 0; xreg <- x(1) ----
    {
        float4 v = *reinterpret_cast<const float4*>(
            &x[(size_t)(n0 + wid) * 128 + lane * 4]);
        float m, rstd; ln_stats(v, m, rstd);
        float4 w4 = reinterpret_cast<const float4*>(ln1w)[lane];
        float4 b4 = reinterpret_cast<const float4*>(ln1b)[lane];
        float4 o4;
        o4.x = (v.x - m) * rstd * w4.x + b4.x;
        o4.y = (v.y - m) * rstd * w4.y + b4.y;
        o4.z = (v.z - m) * rstd * w4.z + b4.z;
        o4.w = (v.w - m) * rstd * w4.w + b4.w;
        sts_h4(sm + SCN_XH, wid, lane * 4, o4, 2);     // xh buf 0
    }
    float4 xreg = *reinterpret_cast<const float4*>(
        &x[((size_t)1 * NN + n0 + wid) * 128 + lane * 4]);   // x(1)

    for (int t = 0; t < TT; t++) {
        // mask h(t), cvt -> hh[t&1]
        h[0][0] *= mn0; h[0][1] *= mn0;
        h[1][0] *= mn1; h[1][1] *= mn1;
        {
            char* hhb = sm + SCN_HH + (t & 1) * HH_BUF;
            #pragma unroll
            for (int ri = 0; ri < 2; ri++) {
                __half2 hp = __floats2half2_rn(h[ri][0], h[ri][1]);
                uint32_t hu; memcpy(&hu, &hp, 4);
                *reinterpret_cast<uint32_t*>(
                    hhb + sw_off(qrow + ri * 8, jbase + qcol, 2)) = hu;
            }
        }
        if (t + 1 < TT) {
            mn0 = masks[(size_t)(t + 1) * NN + n0 + qrow];
            mn1 = masks[(size_t)(t + 1) * NN + n0 + qrow + 8];
        }
        __syncthreads();   // [A] hh(t) + xh(t) (written t-1) + lnt(t-1) visible;
                           //     step t-1 readers of xh[(t+1)&1] have finished

        // LN1(x(t+1)) from xreg -> xh[(t+1)&1]
        // safe: previous readers of that buffer (step t-1's mma) completed before [A]
        {
            float m, rstd; ln_stats(xreg, m, rstd);
            float4 o4 = ln_apply(xreg, m, rstd, sm + SCN_L1W, sm + SCN_L1B, lane);
            sts_h4(sm + SCN_XH + ((t + 1) & 1) * XH_BUF, wid, lane * 4, o4, 2);
        }

        // prefetch x(t+2) into registers
        {
            int t2 = (t + 2 < TT) ? t + 2 : TT - 1;
            xreg = *reinterpret_cast<const float4*>(
                &x[((size_t)t2 * NN + n0 + wid) * 128 + lane * 4]);
        }

        // LN2(t-1)
        if (t > 0) {
            const float* lp = reinterpret_cast<const float*>(
                sm + SCN_LNT + ((t - 1) & 1) * LNT_BUF);
            float4 v = *reinterpret_cast<const float4*>(&lp[wid * 132 + lane * 4]);
            float m, rstd; ln_stats(v, m, rstd);
            float4 o4 = ln_apply(v, m, rstd, sm + SCN_L2W, sm + SCN_L2B, lane);
            *reinterpret_cast<float4*>(
                &out[((size_t)(t - 1) * NN + n0 + wid) * 128 + lane * 4]) = o4;
        }

        // mma: gh(t) from hh[t&1] and gi(t) from xh[t&1];
        // r,z accumulate gi+gh into the SAME accumulator; n kept split
        float4 accR = make_float4(0,0,0,0), accZ = make_float4(0,0,0,0);
        float4 accNh = make_float4(0,0,0,0), accNi = make_float4(0,0,0,0);
        {
            const uint32_t hhB = smb + SCN_HH + (t & 1) * HH_BUF;
            const uint32_t xhB = smb + SCN_XH + (t & 1) * XH_BUF;
            #pragma unroll
            for (int p = 0; p < 4; p++) {
                uint32_t ah[2][4], ax[2][4];
                #pragma unroll
                for (int s = 0; s < 2; s++) {
                    uint32_t aoff = sw_off(a_row, ((p * 2 + s) * 2 + akg) * 8, 2);
                    ldm_x4(ah[s], hhB + aoff);
                    ldm_x4(ax[s], xhB + aoff);
                }
                #pragma unroll
                for (int g = 0; g < 3; g++) {
                    uint32_t bl[4], be[4];
                    uint32_t boff = sw_off(g * 128 + jbase + lr,
                                           ((p * 2 + b_ks_half) * 2 + b_kg) * 8, 48);
                    ldm_x4(bl, smb + SCN_WHH + boff);
                    ldm_x4(be, smb + SCN_WEF + boff);
                    if (g == 0) {
                        mma16816h(accR, ah[0], &bl[0]);
                        mma16816h(accR, ah[1], &bl[2]);
                        mma16816h(accR, ax[0], &be[0]);
                        mma16816h(accR, ax[1], &be[2]);
                    } else if (g == 1) {
                        mma16816h(accZ, ah[0], &bl[0]);
                        mma16816h(accZ, ah[1], &bl[2]);
                        mma16816h(accZ, ax[0], &be[0]);
                        mma16816h(accZ, ax[1], &be[2]);
                    } else {
                        mma16816h(accNh, ah[0], &bl[0]);
                        mma16816h(accNh, ah[1], &bl[2]);
                        mma16816h(accNi, ax[0], &be[0]);
                        mma16816h(accNi, ax[1], &be[2]);
                    }
                }
            }
        }

        // gates (MUFU) + state update; stage h_new for LN2
        {
            float* lnt = reinterpret_cast<float*>(sm + SCN_LNT + (t & 1) * LNT_BUF);
            const float* aR  = reinterpret_cast<const float*>(&accR);
            const float* aZ  = reinterpret_cast<const float*>(&accZ);
            const float* aNi = reinterpret_cast<const float*>(&accNi);
            const float* aNh = reinterpret_cast<const float*>(&accNh);
            #pragma unroll
            for (int ri = 0; ri < 2; ri++) {
                #pragma unroll
                for (int cp = 0; cp < 2; cp++) {
                    int ci = ri * 2 + cp;
                    float r = sigmoid_ap(aR[ci] + brz[0][cp]);
                    float z = sigmoid_ap(aZ[ci] + brz[1][cp]);
                    float nv = tanh_ap((aNi[ci] + bngi[cp]) + r * (aNh[ci] + bngh[cp]));
                    h[ri][cp] = (1.0f - z) * nv + z * h[ri][cp];
                }
                *reinterpret_cast<float2*>(&lnt[(qrow + ri * 8) * 132 + jbase + qcol]) =
                    make_float2(h[ri][0], h[ri][1]);
            }
        }
        // single barrier per step: next iteration's pre-sync writes target the
        // other hh buffer; xh/lnt same-slot rewrites occur after the next [A].
    }

    __syncthreads();
    // final LN2 for t = 127
    {
        const float* lp = reinterpret_cast<const float*>(
            sm + SCN_LNT + ((TT - 1) & 1) * LNT_BUF);
        float4 v = *reinterpret_cast<const float4*>(&lp[wid * 132 + lane * 4]);
        float m, rstd; ln_stats(v, m, rstd);
        float4 o4 = ln_apply(v, m, rstd, sm + SCN_L2W, sm + SCN_L2B, lane);
        *reinterpret_cast<float4*>(
            &out[((size_t)(TT - 1) * NN + n0 + wid) * 128 + lane * 4]) = o4;
    }

    #pragma unroll
    for (int ri = 0; ri < 2; ri++) {
        float2 v = make_float2(h[ri][0], h[ri][1]);
        *reinterpret_cast<float2*>(
            &hT[(size_t)(n0 + qrow + ri * 8) * 128 + jbase + qcol]) = v;
    }
}

// ---------------- launch ----------------
extern "C" void kernel_launch(void* const* d_in, const int* in_sizes, int n_in,
                              void* d_out, int out_size)
{
    const float* x     = (const float*)d_in[0];
    const float* hxs   = (const float*)d_in[1];
    const float* masks = (const float*)d_in[2];
    const float* ln1w  = (const float*)d_in[3];
    const float* ln1b  = (const float*)d_in[4];
    const float* W1    = (const float*)d_in[5];
    const float* b1    = (const float*)d_in[6];
    const float* W2    = (const float*)d_in[7];
    const float* b2    = (const float*)d_in[8];
    const float* Wih   = (const float*)d_in[9];
    const float* bih   = (const float*)d_in[10];
    const float* Whh   = (const float*)d_in[11];
    const float* bhh   = (const float*)d_in[12];
    const float* ln2w  = (const float*)d_in[13];
    const float* ln2b  = (const float*)d_in[14];
    float* out = (float*)d_out;

    float *pm1, *pt1, *pbeff;
    __nv_bfloat16* pws;
    cudaGetSymbolAddress((void**)&pws,   g_ws);
    cudaGetSymbolAddress((void**)&pm1,   g_m1);
    cudaGetSymbolAddress((void**)&pt1,   g_t1);
    cudaGetSymbolAddress((void**)&pbeff, g_beff);

    cudaFuncSetAttribute(scan_mega, cudaFuncAttributeMaxDynamicSharedMemorySize, SCAN_SMEM);

    // 1) compose W_eff (fp32) -> f16; Whh -> f16
    prep_m1<<<384, 128>>>(Wih, W2, b2, pm1, pt1);
    prep_meff<<<384, 128>>>(pm1, W1, b1, bih, pt1, pws, pbeff);
    prep_whh<<<192, 256>>>(Whh, pws);
    // 2) grand fused kernel: fused r/z accumulators, 1 sync/step
    scan_mega<<<NN/16, 512, SCAN_SMEM>>>(x, hxs, masks, pws, pbeff, bhh,
                                         ln1w, ln1b, ln2w, ln2b,
                                         out, out + (size_t)ROWS*128);
}